// round 14
// baseline (speedup 1.0000x reference)
#include <cuda_runtime.h>
#include <math.h>

// Static geometry: x shape (1, 3, 32, 512, 512), patch 32x32
#define C       3
#define T       32
#define H       512
#define W       512
#define PS      32
#define NPATCH  (T * (H/PS) * (W/PS))   // 8192
#define PATCH_ELEMS (C * PS * PS)       // 3072

// One slot per patch: 0.0f = not done; otherwise the (strictly positive)
// patch sum of |x - xr|. Value doubles as the completion flag, so workers
// need NO atomics, NO fences, NO counters. Zero-initialized at module load;
// the finalizer resets consumed slots each iteration -> graph-replay safe.
__device__ float g_patch_sum[NPATCH];

__global__ __launch_bounds__(256, 8)
void patch_loss_kernel(const float* __restrict__ x,
                       const float* __restrict__ xr,
                       float* __restrict__ out) {
    // ---------------- Finalizer CTA (block 0) ----------------
    if (blockIdx.x == 0) {
        const int tid  = threadIdx.x;       // [0,256)
        const int lane = tid & 31;
        const int wid  = tid >> 5;
        // Thread owns 32 contiguous slots = patches [tid*32, tid*32+32),
        // all within frame t = tid >> 3.
        const float4* slots =
            reinterpret_cast<const float4*>(&g_patch_sum[tid * 32]);

        float m = 0.0f;
        // Bounded poll: guarantees termination unconditionally. The bound
        // (~4M passes) is ~4 orders of magnitude beyond what any real run
        // needs (~hundreds of passes), so it never alters results.
        for (unsigned int iter = 0; iter < (1u << 22); ++iter) {
            m = 0.0f;
            float mn = 1.0f;
#pragma unroll
            for (int j = 0; j < 8; ++j) {
                float4 v;
                asm volatile("ld.global.cg.v4.f32 {%0,%1,%2,%3}, [%4];"
                             : "=f"(v.x), "=f"(v.y), "=f"(v.z), "=f"(v.w)
                             : "l"(slots + j) : "memory");
                m  = fmaxf(m,  fmaxf(fmaxf(v.x, v.y), fmaxf(v.z, v.w)));
                mn = fminf(mn, fminf(fminf(v.x, v.y), fminf(v.z, v.w)));
            }
            if (mn > 0.0f) break;           // all 32 slots written
            __nanosleep(128);
        }

        // Reset own (fully consumed) slots for the next graph replay.
        float4* wslots = reinterpret_cast<float4*>(&g_patch_sum[tid * 32]);
        const float4 z = make_float4(0.f, 0.f, 0.f, 0.f);
#pragma unroll
        for (int j = 0; j < 8; ++j) wslots[j] = z;

        // 8 threads per frame -> max within each 8-lane segment.
#pragma unroll
        for (int off = 4; off > 0; off >>= 1)
            m = fmaxf(m, __shfl_down_sync(0xFFFFFFFFu, m, off, 8));

        __shared__ float frame_max[T];      // 32 frames
        if ((lane & 7) == 0)
            frame_max[wid * 4 + (lane >> 3)] = m;
        __syncthreads();

        if (wid == 0) {
            float v = fmaxf(frame_max[lane], 0.0f);   // T == 32 lanes
#pragma unroll
            for (int off = 16; off > 0; off >>= 1)
                v += __shfl_down_sync(0xFFFFFFFFu, v, off);
            if (lane == 0) {
                const float scale = 0.5f / ((float)PATCH_ELEMS * (float)T);
                out[0] = logf(v * scale);
            }
        }
        return;
    }

    // ---------------- Worker CTA: one 32x32 patch ----------------
    const int patch = blockIdx.x - 1;      // [0, 8192)
    const int t   = patch >> 8;            // frame
    const int rem = patch & 255;
    const int ih  = rem >> 4;
    const int iw  = rem & 15;

    const int tid = threadIdx.x;           // [0, 256)
    const int r = tid >> 3;                // row within patch [0,32)
    const int q = tid & 7;                 // float4 index within row [0,8)

    const int hrow  = ih * PS + r;
    const int base0 = (t * H + hrow) * W + iw * PS + q * 4;
    const int cstride = T * H * W;

    float s = 0.0f;
#pragma unroll
    for (int c = 0; c < C; ++c) {
        const int idx = base0 + c * cstride;
        const float4 a = __ldg(reinterpret_cast<const float4*>(x  + idx));
        const float4 b = __ldg(reinterpret_cast<const float4*>(xr + idx));
        s += fabsf(a.x - b.x) + fabsf(a.y - b.y)
           + fabsf(a.z - b.z) + fabsf(a.w - b.w);
    }

    // Block reduction: warp shfl then smem across 8 warps.
#pragma unroll
    for (int off = 16; off > 0; off >>= 1)
        s += __shfl_down_sync(0xFFFFFFFFu, s, off);

    __shared__ float warp_sums[8];
    const int lane = tid & 31;
    const int wid  = tid >> 5;
    if (lane == 0) warp_sums[wid] = s;
    __syncthreads();

    if (wid == 0) {
        float v = (lane < 8) ? warp_sums[lane] : 0.0f;
#pragma unroll
        for (int off = 4; off > 0; off >>= 1)
            v += __shfl_down_sync(0xFFFFFFFFu, v, off);
        if (lane == 0) {
            // Plain fire-and-forget store: value doubles as done-flag
            // (v > 0 always for this data). No ordering needed.
            asm volatile("st.global.cg.f32 [%0], %1;"
                         :: "l"(&g_patch_sum[patch]), "f"(v) : "memory");
        }
    }
}

extern "C" void kernel_launch(void* const* d_in, const int* in_sizes, int n_in,
                              void* d_out, int out_size) {
    const float* x  = (const float*)d_in[0];
    const float* xr = (const float*)d_in[1];
    float* out = (float*)d_out;

    patch_loss_kernel<<<NPATCH + 1, 256>>>(x, xr, out);
}

// round 15
// speedup vs baseline: 1.0516x; 1.0516x over previous
#include <cuda_runtime.h>
#include <math.h>

// Static geometry: x shape (1, 3, 32, 512, 512), patch 32x32
#define C       3
#define T       32
#define H       512
#define W       512
#define PS      32
#define NPATCH  (T * (H/PS) * (W/PS))   // 8192
#define PATCH_ELEMS (C * PS * PS)       // 3072
#define PPB     2                       // patches per worker CTA
#define GRIDW   (NPATCH / PPB)          // 4096 workers (+1 finalizer)

// Float bits of per-frame max patch-sum; sums >= 0 so int-punned atomicMax
// preserves float order and zero-init is the identity. Reset by the
// finalizer each iteration -> graph-replay safe.
__device__ int          g_frame_max[T];   // zero-initialized
__device__ unsigned int g_count;          // zero-initialized

__global__ __launch_bounds__(256, 8)
void patch_loss_kernel(const float* __restrict__ x,
                       const float* __restrict__ xr,
                       float* __restrict__ out) {
    // ---------------- Finalizer CTA (block 0) ----------------
    if (blockIdx.x == 0) {
        const int tid = threadIdx.x;
        if (tid < 32) {
            if (tid == 0) {
                unsigned int c;
                // Bounded spin on ONE word (4B/pass), tight wakeup.
                for (unsigned int it = 0; it < (1u << 24); ++it) {
                    asm volatile("ld.acquire.gpu.global.u32 %0, [%1];"
                                 : "=r"(c) : "l"(&g_count) : "memory");
                    if (c >= (unsigned int)GRIDW) break;
                    __nanosleep(32);
                }
            }
            __syncwarp();
            // Acquire pairs with workers' release-adds: all RED.MAXs visible.
            float fm = fmaxf(__int_as_float(__ldcg(&g_frame_max[tid])), 0.0f);
#pragma unroll
            for (int off = 16; off > 0; off >>= 1)
                fm += __shfl_down_sync(0xFFFFFFFFu, fm, off);

            // Reset device state for the next graph replay.
            g_frame_max[tid] = 0;
            if (tid == 0) {
                g_count = 0u;
                const float scale = 0.5f / ((float)PATCH_ELEMS * (float)T);
                out[0] = logf(fm * scale);
            }
        }
        return;
    }

    // ---------- Worker CTA: TWO adjacent 32x32 patches ----------
    const int base  = (blockIdx.x - 1) * PPB;   // first patch (even)
    const int t     = base >> 8;                // frame (shared)
    const int rem   = base & 255;
    const int ih    = rem >> 4;                 // row band (shared)
    const int iw0   = rem & 15;                 // even; pair = iw0, iw0+1

    const int tid = threadIdx.x;                // [0, 256)
    const int r = tid >> 3;                     // row within patch [0,32)
    const int q = tid & 7;                      // float4 within row [0,8)

    const int hrow  = ih * PS + r;
    const int idx0  = (t * H + hrow) * W + iw0 * PS + q * 4;  // patch A
    const int cstride = T * H * W;

    float s0 = 0.0f, s1 = 0.0f;
#pragma unroll
    for (int c = 0; c < C; ++c) {
        const int ia = idx0 + c * cstride;      // patch A
        const int ib = ia + PS;                 // patch B (+32 floats)
        const float4 ax = __ldg(reinterpret_cast<const float4*>(x  + ia));
        const float4 ar = __ldg(reinterpret_cast<const float4*>(xr + ia));
        const float4 bx = __ldg(reinterpret_cast<const float4*>(x  + ib));
        const float4 br = __ldg(reinterpret_cast<const float4*>(xr + ib));
        s0 += fabsf(ax.x - ar.x) + fabsf(ax.y - ar.y)
            + fabsf(ax.z - ar.z) + fabsf(ax.w - ar.w);
        s1 += fabsf(bx.x - br.x) + fabsf(bx.y - br.y)
            + fabsf(bx.z - br.z) + fabsf(bx.w - br.w);
    }

    // Warp reduce both accumulators.
#pragma unroll
    for (int off = 16; off > 0; off >>= 1) {
        s0 += __shfl_down_sync(0xFFFFFFFFu, s0, off);
        s1 += __shfl_down_sync(0xFFFFFFFFu, s1, off);
    }

    __shared__ float warp_sums[2][8];           // [patch][warp]
    const int lane = tid & 31;
    const int wid  = tid >> 5;
    if (lane == 0) { warp_sums[0][wid] = s0; warp_sums[1][wid] = s1; }
    __syncthreads();

    if (wid == 0) {
        // 16 partials in lanes 0..15: lane -> patch = lane>>3, warp = lane&7
        float v = (lane < 16) ? warp_sums[lane >> 3][lane & 7] : 0.0f;
#pragma unroll
        for (int off = 4; off > 0; off >>= 1)
            v += __shfl_down_sync(0xFFFFFFFFu, v, off);
        // Lanes 0 and 8 hold the two patch sums.
        if ((lane & 7) == 0 && lane < 16) {
            // fire-and-forget RED.MAX (v >= 0 -> int cmp == float cmp)
            atomicMax(&g_frame_max[t], __float_as_int(v));
        }
        if (lane == 0) {
            // release orders the two RED.MAXs before the count bump;
            // no return value -> no round-trip register wait.
            asm volatile("red.release.gpu.global.add.u32 [%0], 1;"
                         :: "l"(&g_count) : "memory");
        }
    }
}

extern "C" void kernel_launch(void* const* d_in, const int* in_sizes, int n_in,
                              void* d_out, int out_size) {
    const float* x  = (const float*)d_in[0];
    const float* xr = (const float*)d_in[1];
    float* out = (float*)d_out;

    patch_loss_kernel<<<GRIDW + 1, 256>>>(x, xr, out);
}